// round 2
// baseline (speedup 1.0000x reference)
#include <cuda_runtime.h>
#include <cstdint>

// ---------------------------------------------------------------------------
// TransitionLayer: out[b,i,j] = softmax_j( log(clip(g,1e-6))/0.5 + mask ), j>=i
//   g[b,i,j] = 1 - prod_r (1 - alpha[i,j,r] * clause[b,i,j,r])
//   clause   = prod_m ( A[i,j,r,m] + C[i,j,r,m] * u[b,m] )
//   A = s0+s2, C = s1-s2, s = softmax(sel/0.8, axis=-1)
// softmax(log g / 0.5) == normalize(g^2); j<i entries are exactly 0;
// row_has_finite is always true (diagonal is finite).
//
// Partitioning: 5 rowsets {0,9},{1,8},{2,7},{3,6},{4,5} — 11 pairs each.
// Block = 64 threads = one rowset x 64 batch-packs; thread = 2 batches via
// packed fma.rn.f32x2. Row index is a compile-time template param.
// ---------------------------------------------------------------------------

#define NPAIR 55
#define NCOEF 2420   // 55 pairs * 22 m * 2 r   (float4 {A,A,C,C} each)
#define NALPHA 110   // 55 pairs * 2 r

__device__ __constant__ int c_PAIR_I[NPAIR] = {
    0,0,0,0,0,0,0,0,0,0,
    1,1,1,1,1,1,1,1,1,
    2,2,2,2,2,2,2,2,
    3,3,3,3,3,3,3,
    4,4,4,4,4,4,
    5,5,5,5,5,
    6,6,6,6,
    7,7,7,
    8,8,
    9};
__device__ __constant__ int c_PAIR_J[NPAIR] = {
    0,1,2,3,4,5,6,7,8,9,
    1,2,3,4,5,6,7,8,9,
    2,3,4,5,6,7,8,9,
    3,4,5,6,7,8,9,
    4,5,6,7,8,9,
    5,6,7,8,9,
    6,7,8,9,
    7,8,9,
    8,9,
    9};
// global pair indices per rowset (row I0 pairs first, then row I1 pairs)
__device__ __constant__ int c_GPAIR[5][11] = {
    { 0, 1, 2, 3, 4, 5, 6, 7, 8, 9, 54},   // rows {0,9}
    {10,11,12,13,14,15,16,17,18,52,53},    // rows {1,8}
    {19,20,21,22,23,24,25,26,49,50,51},    // rows {2,7}
    {27,28,29,30,31,32,33,45,46,47,48},    // rows {3,6}
    {34,35,36,37,38,39,40,41,42,43,44}};   // rows {4,5}

// scratch (computed once per graph replay by tl_prep)
__device__ float4 g_coef4[NCOEF];   // [p*44 + m*2 + r] = {A,A,C,C}
__device__ float2 g_alpha2[NALPHA]; // [p*2 + r] = {alpha,alpha}

// ---------------- packed f32x2 helpers ----------------
__device__ __forceinline__ unsigned long long pk2(float lo, float hi) {
    unsigned long long r;
    asm("mov.b64 %0, {%1, %2};" : "=l"(r) : "f"(lo), "f"(hi));
    return r;
}
__device__ __forceinline__ void upk2(unsigned long long v, float& lo, float& hi) {
    asm("mov.b64 {%0, %1}, %2;" : "=f"(lo), "=f"(hi) : "l"(v));
}
#define FMA2(d, a, b, c) \
    asm("fma.rn.f32x2 %0, %1, %2, %3;" : "=l"(d) : "l"(a), "l"(b), "l"(c))
#define MUL2(d, a, b) \
    asm("mul.rn.f32x2 %0, %1, %2;" : "=l"(d) : "l"(a), "l"(b))

// ---------------- kernel 1: coefficient precompute (tiny) ----------------
__global__ void tl_prep(const float* __restrict__ sel,
                        const float* __restrict__ alog) {
    int e = blockIdx.x * blockDim.x + threadIdx.x;
    if (e < NCOEF) {
        int p   = e / 44;
        int rem = e - p * 44;
        int m   = rem >> 1;
        int r   = rem & 1;
        int i = c_PAIR_I[p], j = c_PAIR_J[p];
        int base = (((i * 10 + j) * 2 + r) * 22 + m) * 3;
        float s0 = sel[base + 0] * 1.25f;
        float s1 = sel[base + 1] * 1.25f;
        float s2 = sel[base + 2] * 1.25f;
        float mx = fmaxf(s0, fmaxf(s1, s2));
        float e0 = expf(s0 - mx), e1 = expf(s1 - mx), e2 = expf(s2 - mx);
        float inv = 1.0f / (e0 + e1 + e2);
        float A = (e0 + e2) * inv;   // softmax0 + softmax2
        float C = (e1 - e2) * inv;   // softmax1 - softmax2
        g_coef4[e] = make_float4(A, A, C, C);
    }
    if (e < NALPHA) {
        int p = e >> 1;
        int r = e & 1;
        int i = c_PAIR_I[p], j = c_PAIR_J[p];
        float a = alog[(i * 10 + j) * 2 + r];
        float s = 1.0f / (1.0f + expf(-a));
        g_alpha2[e] = make_float2(s, s);
    }
}

// ---------------- per-row worker (I and local pair base LB compile-time) ---
template<int I, int LB>
__device__ __forceinline__ void do_row(const ulonglong2* __restrict__ scq,
                                       const unsigned long long* __restrict__ sa,
                                       const unsigned long long* __restrict__ u2,
                                       float* __restrict__ outb) {
    const unsigned long long ONE  = pk2(1.0f, 1.0f);
    const unsigned long long NEG1 = pk2(-1.0f, -1.0f);
    unsigned long long w[10 - I];
    float sx = 0.0f, sy = 0.0f;
#pragma unroll
    for (int jj = 0; jj < 10 - I; jj++) {
        const ulonglong2* cp = scq + (LB + jj) * 44;  // [(m)*2 + r]
        unsigned long long cl0 = ONE, cl1 = ONE;
#pragma unroll
        for (int m = 0; m < 22; m++) {
            ulonglong2 k0 = cp[2 * m + 0];  // {A,A},{C,C} for r=0
            ulonglong2 k1 = cp[2 * m + 1];  // {A,A},{C,C} for r=1
            unsigned long long l0, l1;
            FMA2(l0, k0.y, u2[m], k0.x);
            FMA2(l1, k1.y, u2[m], k1.x);
            MUL2(cl0, cl0, l0);
            MUL2(cl1, cl1, l1);
        }
        // g = 1 - (1 - a0*cl0)(1 - a1*cl1) = x + y*(1-x)
        unsigned long long x, y, omx, g;
        MUL2(x, sa[(LB + jj) * 2 + 0], cl0);
        MUL2(y, sa[(LB + jj) * 2 + 1], cl1);
        FMA2(omx, x, NEG1, ONE);
        FMA2(g, y, omx, x);
        float gx, gy;
        upk2(g, gx, gy);
        gx = fmaxf(gx, 1e-6f);  gy = fmaxf(gy, 1e-6f);
        gx *= gx;               gy *= gy;    // softmax(logit/0.5) ~ g^2
        sx += gx;               sy += gy;
        w[jj] = pk2(gx, gy);
    }
    const float ix = 1.0f / sx;
    const float iy = 1.0f / sy;
    float v0[10], v1[10];
#pragma unroll
    for (int j = 0; j < 10; j++) { v0[j] = 0.0f; v1[j] = 0.0f; }
#pragma unroll
    for (int jj = 0; jj < 10 - I; jj++) {
        float a, b;
        upk2(w[jj], a, b);
        v0[I + jj] = a * ix;
        v1[I + jj] = b * iy;
    }
    // rows are 40B, 8B-aligned -> float2 stores
    float2* p0 = reinterpret_cast<float2*>(outb + I * 10);
    float2* p1 = reinterpret_cast<float2*>(outb + 100 + I * 10);
#pragma unroll
    for (int k = 0; k < 5; k++) {
        p0[k] = make_float2(v0[2 * k], v0[2 * k + 1]);
        p1[k] = make_float2(v1[2 * k], v1[2 * k + 1]);
    }
}

// ---------------- kernel 2: main ----------------
// grid = 640 blocks x 64 threads; block -> (rowset, 64 batch-packs)
__global__ __launch_bounds__(64) void tl_main(const float* __restrict__ pred,
                                              float* __restrict__ out) {
    __shared__ float4 s_coef[11 * 44];            // 7.7 KB
    __shared__ unsigned long long s_alpha[22];    // 176 B

    const int tid    = threadIdx.x;
    const int rowset = blockIdx.x % 5;
    const int qblk   = blockIdx.x / 5;

    // stage this rowset's 11 pairs into SMEM
    for (int e = tid; e < 11 * 44; e += 64) {
        int lp  = e / 44;
        int rem = e - lp * 44;
        s_coef[e] = g_coef4[c_GPAIR[rowset][lp] * 44 + rem];
    }
    if (tid < 22) {
        const unsigned long long* ga =
            reinterpret_cast<const unsigned long long*>(g_alpha2);
        s_alpha[tid] = ga[c_GPAIR[rowset][tid >> 1] * 2 + (tid & 1)];
    }
    __syncthreads();

    const int q = qblk * 64 + tid;       // batch pack: batches 2q, 2q+1

    // load u for both batches (44 contiguous floats, 16B-aligned)
    float f[44];
    const float4* pv = reinterpret_cast<const float4*>(pred + (size_t)q * 44);
#pragma unroll
    for (int k = 0; k < 11; k++) {
        float4 t = pv[k];
        f[4 * k + 0] = t.x; f[4 * k + 1] = t.y;
        f[4 * k + 2] = t.z; f[4 * k + 3] = t.w;
    }
    unsigned long long u2[22];
#pragma unroll
    for (int m = 0; m < 22; m++) u2[m] = pk2(f[m], f[22 + m]);

    const ulonglong2* scq = reinterpret_cast<const ulonglong2*>(s_coef);
    float* outb = out + (size_t)q * 200;

    switch (rowset) {
        case 0: do_row<0, 0>(scq, s_alpha, u2, outb);
                do_row<9,10>(scq, s_alpha, u2, outb); break;
        case 1: do_row<1, 0>(scq, s_alpha, u2, outb);
                do_row<8, 9>(scq, s_alpha, u2, outb); break;
        case 2: do_row<2, 0>(scq, s_alpha, u2, outb);
                do_row<7, 8>(scq, s_alpha, u2, outb); break;
        case 3: do_row<3, 0>(scq, s_alpha, u2, outb);
                do_row<6, 7>(scq, s_alpha, u2, outb); break;
        case 4: do_row<4, 0>(scq, s_alpha, u2, outb);
                do_row<5, 6>(scq, s_alpha, u2, outb); break;
    }
}

extern "C" void kernel_launch(void* const* d_in, const int* in_sizes, int n_in,
                              void* d_out, int out_size) {
    const float* pred = (const float*)d_in[0];  // (16384, 22) f32
    const float* sel  = (const float*)d_in[1];  // (10,10,2,22,3) f32
    const float* alog = (const float*)d_in[2];  // (10,10,2) f32
    float* out = (float*)d_out;                 // (16384, 10, 10) f32

    tl_prep<<<(NCOEF + 127) / 128, 128>>>(sel, alog);
    tl_main<<<640, 64>>>(pred, out);
}

// round 9
// speedup vs baseline: 1.1574x; 1.1574x over previous
#include <cuda_runtime.h>
#include <cstdint>

// ---------------------------------------------------------------------------
// TransitionLayer: out[b,i,j] = softmax_j( log(clip(g,1e-6))/0.5 + mask ), j>=i
//   g[b,i,j] = 1 - prod_r (1 - alpha[i,j,r] * clause[b,i,j,r])
//   clause   = prod_m ( A[i,j,r,m] + C[i,j,r,m] * u[b,m] )
//   A = s0+s2, C = s1-s2, s = softmax(sel/0.8, axis=-1)
// softmax(log g / 0.5) == normalize(g^2); j<i entries are exactly 0.
//
// SINGLE kernel: each block recomputes its own row's coefficients from
// sel/alog directly into smem (<=440 entries, ~3/thread) — no prep kernel,
// no global scratch, one graph node.
// Partitioning: thread = (batch-pack, ONE row). 10 rows x 64 pack-blocks
// = 640 blocks x 128 threads = 2560 warps. Clause product uses TWO
// independent partial accumulators per r to halve the serial MUL chain.
// ---------------------------------------------------------------------------

// ---------------- packed f32x2 helpers ----------------
__device__ __forceinline__ unsigned long long pk2(float lo, float hi) {
    unsigned long long r;
    asm("mov.b64 %0, {%1, %2};" : "=l"(r) : "f"(lo), "f"(hi));
    return r;
}
__device__ __forceinline__ void upk2(unsigned long long v, float& lo, float& hi) {
    asm("mov.b64 {%0, %1}, %2;" : "=f"(lo), "=f"(hi) : "l"(v));
}
#define FMA2(d, a, b, c) \
    asm("fma.rn.f32x2 %0, %1, %2, %3;" : "=l"(d) : "l"(a), "l"(b), "l"(c))
#define MUL2(d, a, b) \
    asm("mul.rn.f32x2 %0, %1, %2;" : "=l"(d) : "l"(a), "l"(b))

// ---------------- per-row worker: whole block handles row I ---------------
template<int I>
__device__ __forceinline__ void row_body(const float* __restrict__ pred,
                                         const float* __restrict__ sel,
                                         const float* __restrict__ alog,
                                         float* __restrict__ out,
                                         int qblk) {
    constexpr int NP = 10 - I;                // pairs in this row: (I,I)..(I,9)
    __shared__ float4 s_coef[NP * 44];        // [(lp)*44 + m*2 + r] = {A,A,C,C}
    __shared__ unsigned long long s_alpha[2 * NP];

    const int tid = threadIdx.x;

    // ---- fused coefficient computation (replaces the old prep kernel) ----
    // entry e = lp*44 + m*2 + r, pair (I, I+lp)
#pragma unroll 1
    for (int e = tid; e < NP * 44; e += 128) {
        int lp  = e / 44;
        int rem = e - lp * 44;
        int m   = rem >> 1;
        int r   = rem & 1;
        int j   = I + lp;
        int base = (((I * 10 + j) * 2 + r) * 22 + m) * 3;
        float s0 = sel[base + 0] * 1.25f;
        float s1 = sel[base + 1] * 1.25f;
        float s2 = sel[base + 2] * 1.25f;
        float mx = fmaxf(s0, fmaxf(s1, s2));
        float e0 = expf(s0 - mx), e1 = expf(s1 - mx), e2 = expf(s2 - mx);
        float inv = 1.0f / (e0 + e1 + e2);
        float A = (e0 + e2) * inv;   // softmax0 + softmax2
        float C = (e1 - e2) * inv;   // softmax1 - softmax2
        s_coef[e] = make_float4(A, A, C, C);
    }
    if (tid < 2 * NP) {
        int lp = tid >> 1;
        int r  = tid & 1;
        float a = alog[((I * 10) + I + lp) * 2 + r];
        float s = 1.0f / (1.0f + expf(-a));
        s_alpha[tid] = pk2(s, s);
    }
    __syncthreads();

    const int q = qblk * 128 + tid;   // batch pack: batches 2q, 2q+1

    // load u for both batches (44 contiguous floats, 16B-aligned)
    float f[44];
    const float4* __restrict__ pv =
        reinterpret_cast<const float4*>(pred + (size_t)q * 44);
#pragma unroll
    for (int k = 0; k < 11; k++) {
        float4 t = pv[k];
        f[4 * k + 0] = t.x; f[4 * k + 1] = t.y;
        f[4 * k + 2] = t.z; f[4 * k + 3] = t.w;
    }
    unsigned long long u2[22];
#pragma unroll
    for (int m = 0; m < 22; m++) u2[m] = pk2(f[m], f[22 + m]);

    const unsigned long long ONE  = pk2(1.0f, 1.0f);
    const unsigned long long NEG1 = pk2(-1.0f, -1.0f);
    const ulonglong2* scq = reinterpret_cast<const ulonglong2*>(s_coef);

    unsigned long long w[NP];
    float sx = 0.0f, sy = 0.0f;
#pragma unroll
    for (int jj = 0; jj < NP; jj++) {
        const ulonglong2* cp = scq + jj * 44;   // [(m)*2 + r]
        // two independent partial products per r -> halves dep-chain latency
        unsigned long long c0a = ONE, c0b = ONE, c1a = ONE, c1b = ONE;
#pragma unroll
        for (int m = 0; m < 22; m += 2) {
            ulonglong2 k0  = cp[2 * m + 0];
            ulonglong2 k1  = cp[2 * m + 1];
            ulonglong2 k0n = cp[2 * m + 2];
            ulonglong2 k1n = cp[2 * m + 3];
            unsigned long long l0, l1, l0n, l1n;
            FMA2(l0,  k0.y,  u2[m],     k0.x);
            FMA2(l1,  k1.y,  u2[m],     k1.x);
            FMA2(l0n, k0n.y, u2[m + 1], k0n.x);
            FMA2(l1n, k1n.y, u2[m + 1], k1n.x);
            MUL2(c0a, c0a, l0);
            MUL2(c1a, c1a, l1);
            MUL2(c0b, c0b, l0n);
            MUL2(c1b, c1b, l1n);
        }
        unsigned long long cl0, cl1;
        MUL2(cl0, c0a, c0b);
        MUL2(cl1, c1a, c1b);
        // g = 1 - (1-a0*cl0)(1-a1*cl1) = x + y*(1-x)
        unsigned long long x, y, omx, g;
        MUL2(x, s_alpha[2 * jj + 0], cl0);
        MUL2(y, s_alpha[2 * jj + 1], cl1);
        FMA2(omx, x, NEG1, ONE);
        FMA2(g, y, omx, x);
        float gx, gy;
        upk2(g, gx, gy);
        gx = fmaxf(gx, 1e-6f);  gy = fmaxf(gy, 1e-6f);
        gx *= gx;               gy *= gy;       // softmax(logit/0.5) == norm g^2
        sx += gx;               sy += gy;
        w[jj] = pk2(gx, gy);
    }
    const float ix = 1.0f / sx;
    const float iy = 1.0f / sy;

    float v0[10], v1[10];
#pragma unroll
    for (int j = 0; j < 10; j++) { v0[j] = 0.0f; v1[j] = 0.0f; }
#pragma unroll
    for (int jj = 0; jj < NP; jj++) {
        float a, b;
        upk2(w[jj], a, b);
        v0[I + jj] = a * ix;
        v1[I + jj] = b * iy;
    }
    // 40B rows, 8B-aligned -> float2 stores
    float* outb = out + (size_t)q * 200;
    float2* p0 = reinterpret_cast<float2*>(outb + I * 10);
    float2* p1 = reinterpret_cast<float2*>(outb + 100 + I * 10);
#pragma unroll
    for (int k = 0; k < 5; k++) {
        p0[k] = make_float2(v0[2 * k], v0[2 * k + 1]);
        p1[k] = make_float2(v1[2 * k], v1[2 * k + 1]);
    }
}

// ---------------- single fused kernel ----------------
// grid = 640 blocks x 128 threads; block -> (row = bid%10, packblk = bid/10)
__global__ __launch_bounds__(128) void tl_main(const float* __restrict__ pred,
                                               const float* __restrict__ sel,
                                               const float* __restrict__ alog,
                                               float* __restrict__ out) {
    const int row  = blockIdx.x % 10;
    const int qblk = blockIdx.x / 10;
    switch (row) {
        case 0: row_body<0>(pred, sel, alog, out, qblk); break;
        case 1: row_body<1>(pred, sel, alog, out, qblk); break;
        case 2: row_body<2>(pred, sel, alog, out, qblk); break;
        case 3: row_body<3>(pred, sel, alog, out, qblk); break;
        case 4: row_body<4>(pred, sel, alog, out, qblk); break;
        case 5: row_body<5>(pred, sel, alog, out, qblk); break;
        case 6: row_body<6>(pred, sel, alog, out, qblk); break;
        case 7: row_body<7>(pred, sel, alog, out, qblk); break;
        case 8: row_body<8>(pred, sel, alog, out, qblk); break;
        case 9: row_body<9>(pred, sel, alog, out, qblk); break;
    }
}

extern "C" void kernel_launch(void* const* d_in, const int* in_sizes, int n_in,
                              void* d_out, int out_size) {
    const float* pred = (const float*)d_in[0];  // (16384, 22) f32
    const float* sel  = (const float*)d_in[1];  // (10,10,2,22,3) f32
    const float* alog = (const float*)d_in[2];  // (10,10,2) f32
    float* out = (float*)d_out;                 // (16384, 10, 10) f32

    tl_main<<<640, 128>>>(pred, sel, alog, out);
}

// round 10
// speedup vs baseline: 1.5405x; 1.3311x over previous
#include <cuda_runtime.h>
#include <cstdint>

// ---------------------------------------------------------------------------
// TransitionLayer: out[b,i,j] = softmax_j( log(clip(g,1e-6))/0.5 + mask ), j>=i
//   g[b,i,j] = 1 - prod_r (1 - alpha[i,j,r] * clause[b,i,j,r])
//   clause   = prod_m ( A[i,j,r,m] + C[i,j,r,m] * u[b,m] )
//   A = s0+s2, C = s1-s2, s = softmax(sel/0.8, axis=-1)
// softmax(log g / 0.5) == normalize(g^2); j<i entries are exactly 0.
//
// R10: ONE batch per thread, scalar fp32. 10 rows x 128 batch-blocks
// = 1280 blocks x 128 threads = 5120 warps (~54% occ) — latency hiding is
// the binding constraint per R9 ncu (occ 19%, issue 16%, all pipes <10%).
// Coefficients recomputed per block into smem ({A0,C0,A1,C1} float4 per
// (pair,m)); single kernel, single graph node.
// ---------------------------------------------------------------------------

// ---------------- per-row worker: whole block handles row I ---------------
template<int I>
__device__ __forceinline__ void row_body(const float* __restrict__ pred,
                                         const float* __restrict__ sel,
                                         const float* __restrict__ alog,
                                         float* __restrict__ out,
                                         int qblk) {
    constexpr int NP = 10 - I;            // pairs in this row: (I,I)..(I,9)
    __shared__ float4 s_coef[NP * 22];    // [lp*22+m] = {A_r0, C_r0, A_r1, C_r1}
    __shared__ float  s_alpha[2 * NP];    // [lp*2+r]

    const int tid = threadIdx.x;

    // ---- fused coefficient computation (both r per entry) ----
#pragma unroll 1
    for (int e = tid; e < NP * 22; e += 128) {
        int lp = e / 22;
        int m  = e - lp * 22;
        int j  = I + lp;
        float AC[4];
#pragma unroll
        for (int r = 0; r < 2; r++) {
            int base = (((I * 10 + j) * 2 + r) * 22 + m) * 3;
            float s0 = sel[base + 0] * 1.25f;
            float s1 = sel[base + 1] * 1.25f;
            float s2 = sel[base + 2] * 1.25f;
            float mx = fmaxf(s0, fmaxf(s1, s2));
            float e0 = expf(s0 - mx), e1 = expf(s1 - mx), e2 = expf(s2 - mx);
            float inv = 1.0f / (e0 + e1 + e2);
            AC[2 * r + 0] = (e0 + e2) * inv;   // A = softmax0 + softmax2
            AC[2 * r + 1] = (e1 - e2) * inv;   // C = softmax1 - softmax2
        }
        s_coef[e] = make_float4(AC[0], AC[1], AC[2], AC[3]);
    }
    if (tid < 2 * NP) {
        int lp = tid >> 1;
        int r  = tid & 1;
        float a = alog[((I * 10) + I + lp) * 2 + r];
        s_alpha[tid] = 1.0f / (1.0f + expf(-a));
    }
    __syncthreads();

    const int b = qblk * 128 + tid;   // batch 0..16383

    // load u: 22 contiguous floats, rows are 88B (8B-aligned) -> float2
    float u[22];
    {
        const float2* __restrict__ pv =
            reinterpret_cast<const float2*>(pred + (size_t)b * 22);
#pragma unroll
        for (int k = 0; k < 11; k++) {
            float2 t = pv[k];
            u[2 * k + 0] = t.x;
            u[2 * k + 1] = t.y;
        }
    }

    float w[NP];
    float sum = 0.0f;
#pragma unroll
    for (int jj = 0; jj < NP; jj++) {
        const float4* cp = s_coef + jj * 22;
        // two independent partial products per r -> halve the serial chain
        float c0a = 1.0f, c0b = 1.0f, c1a = 1.0f, c1b = 1.0f;
#pragma unroll
        for (int m = 0; m < 22; m += 2) {
            float4 k0 = cp[m];
            float4 k1 = cp[m + 1];
            float l0a = fmaf(k0.y, u[m],     k0.x);
            float l1a = fmaf(k0.w, u[m],     k0.z);
            float l0b = fmaf(k1.y, u[m + 1], k1.x);
            float l1b = fmaf(k1.w, u[m + 1], k1.z);
            c0a *= l0a;  c1a *= l1a;
            c0b *= l0b;  c1b *= l1b;
        }
        float cl0 = c0a * c0b;
        float cl1 = c1a * c1b;
        // g = 1 - (1-a0*cl0)(1-a1*cl1) = x + y*(1-x)
        float x = s_alpha[2 * jj + 0] * cl0;
        float y = s_alpha[2 * jj + 1] * cl1;
        float g = fmaf(y, 1.0f - x, x);
        g = fmaxf(g, 1e-6f);
        g = g * g;                     // softmax(logit/0.5) == normalize(g^2)
        sum += g;
        w[jj] = g;
    }
    const float inv = 1.0f / sum;

    float v[10];
#pragma unroll
    for (int j = 0; j < 10; j++) v[j] = 0.0f;
#pragma unroll
    for (int jj = 0; jj < NP; jj++) v[I + jj] = w[jj] * inv;

    // 40B output row, 8B-aligned -> 5 float2 stores
    float2* p = reinterpret_cast<float2*>(out + (size_t)b * 100 + I * 10);
#pragma unroll
    for (int k = 0; k < 5; k++)
        p[k] = make_float2(v[2 * k], v[2 * k + 1]);
}

// ---------------- single fused kernel ----------------
// grid = 1280 blocks x 128 threads; block -> (row = bid%10, batchblk = bid/10)
__global__ __launch_bounds__(128) void tl_main(const float* __restrict__ pred,
                                               const float* __restrict__ sel,
                                               const float* __restrict__ alog,
                                               float* __restrict__ out) {
    const int row  = blockIdx.x % 10;
    const int qblk = blockIdx.x / 10;
    switch (row) {
        case 0: row_body<0>(pred, sel, alog, out, qblk); break;
        case 1: row_body<1>(pred, sel, alog, out, qblk); break;
        case 2: row_body<2>(pred, sel, alog, out, qblk); break;
        case 3: row_body<3>(pred, sel, alog, out, qblk); break;
        case 4: row_body<4>(pred, sel, alog, out, qblk); break;
        case 5: row_body<5>(pred, sel, alog, out, qblk); break;
        case 6: row_body<6>(pred, sel, alog, out, qblk); break;
        case 7: row_body<7>(pred, sel, alog, out, qblk); break;
        case 8: row_body<8>(pred, sel, alog, out, qblk); break;
        case 9: row_body<9>(pred, sel, alog, out, qblk); break;
    }
}

extern "C" void kernel_launch(void* const* d_in, const int* in_sizes, int n_in,
                              void* d_out, int out_size) {
    const float* pred = (const float*)d_in[0];  // (16384, 22) f32
    const float* sel  = (const float*)d_in[1];  // (10,10,2,22,3) f32
    const float* alog = (const float*)d_in[2];  // (10,10,2) f32
    float* out = (float*)d_out;                 // (16384, 10, 10) f32

    tl_main<<<1280, 128>>>(pred, sel, alog, out);
}